// round 14
// baseline (speedup 1.0000x reference)
#include <cuda_runtime.h>
#include <math.h>

#define Bn 32
#define Tn 512
#define Hn 2048
#define Kn 128
#define TPC 32            // gemm blocks per time-chunk (one per batch)

// Scratch (no allocations allowed)
__device__ float g_logits[Bn * Tn * Kn];   // 8 MB
__device__ float g_llh[Bn];
__device__ int   g_cnt[8];                 // chunk completion counters

#define SMEM_BYTES (1024 + (Tn - 1) * Kn)

__global__ void init_kernel()
{
    if (threadIdx.x < 8) g_cnt[threadIdx.x] = 0;
}

// ---------------------------------------------------------------------------
// GEMM (R1 config: BM=64, BN=128, BK=16, 256 thr, 8x4/thread).
// Block bid -> batch b = bid&31, chunk c = bid>>5, rows [b*512+c*64, +64).
// Chunk-major launch order: blocks 0..31 produce chunk 0 for all batches.
// ---------------------------------------------------------------------------
__global__ __launch_bounds__(256) void gemm_kernel(
    const float* __restrict__ hid, const float* __restrict__ W,
    const float* __restrict__ bias)
{
    __shared__ float As[16][64];
    __shared__ float Bs[16][128];

    const int tid = threadIdx.x;
    const int b   = blockIdx.x & 31;
    const int c   = blockIdx.x >> 5;
    const int m0  = b * Tn + c * 64;
    const int ty  = tid >> 5;
    const int tx  = tid & 31;

    float acc[8][4];
#pragma unroll
    for (int i = 0; i < 8; i++)
#pragma unroll
        for (int jj = 0; jj < 4; jj++) acc[i][jj] = 0.f;

    const int arow = tid >> 2;
    const int ac4  = (tid & 3) * 4;

    for (int k0 = 0; k0 < Hn; k0 += 16) {
        float4 a4 = *(const float4*)(hid + (size_t)(m0 + arow) * Hn + k0 + ac4);
        As[ac4 + 0][arow] = a4.x;
        As[ac4 + 1][arow] = a4.y;
        As[ac4 + 2][arow] = a4.z;
        As[ac4 + 3][arow] = a4.w;
        {
            int idx = tid;
            int r = idx >> 5, cc = (idx & 31) * 4;
            *(float4*)(&Bs[r][cc]) = *(const float4*)(W + (size_t)(k0 + r) * Kn + cc);
            idx = tid + 256;
            r = idx >> 5; cc = (idx & 31) * 4;
            *(float4*)(&Bs[r][cc]) = *(const float4*)(W + (size_t)(k0 + r) * Kn + cc);
        }
        __syncthreads();

#pragma unroll
        for (int k = 0; k < 16; k++) {
            float4 b4 = *(const float4*)(&Bs[k][tx * 4]);
            float a[8];
#pragma unroll
            for (int i = 0; i < 8; i++) a[i] = As[k][ty * 8 + i];
#pragma unroll
            for (int i = 0; i < 8; i++) {
                acc[i][0] += a[i] * b4.x;
                acc[i][1] += a[i] * b4.y;
                acc[i][2] += a[i] * b4.z;
                acc[i][3] += a[i] * b4.w;
            }
        }
        __syncthreads();
    }

    const int n0 = tx * 4;
    float4 bb = *(const float4*)(bias + n0);
#pragma unroll
    for (int i = 0; i < 8; i++) {
        int row = m0 + ty * 8 + i;
        float4 o;
        o.x = acc[i][0] + bb.x;
        o.y = acc[i][1] + bb.y;
        o.z = acc[i][2] + bb.z;
        o.w = acc[i][3] + bb.w;
        *(float4*)(g_logits + (size_t)row * Kn + n0) = o;
    }

    __threadfence();
    __syncthreads();
    if (tid == 0) atomicAdd(&g_cnt[c], 1);
}

__device__ __forceinline__ void wait_chunk(int c, int tid)
{
    if (tid == 0) {
        while (((volatile int*)g_cnt)[c] < TPC) __nanosleep(200);
    }
    __syncthreads();
    __threadfence();
}

// ---------------------------------------------------------------------------
// CRF (R1/R4 combined kernel + chunk gating). 64 blocks x 256 threads.
// blocks [0,32): forward; blocks [32,64): viterbi.
// ---------------------------------------------------------------------------
__global__ __launch_bounds__(256) void crf_kernel(
    const int* __restrict__ mask, const int* __restrict__ labels,
    const float* __restrict__ startT, const float* __restrict__ endT,
    const float* __restrict__ trans, float* __restrict__ out)
{
    extern __shared__ char smem[];
    float* sh_s   = (float*)smem;                 // 128 floats
    float* shred  = (float*)(smem + 512);
    int*   shredi = (int*)(smem + 512 + 256);
    unsigned char* bp = (unsigned char*)(smem + 1024);

    const int tid = threadIdx.x;
    const int j = tid >> 1, h = tid & 1;
    const unsigned FULL = 0xFFFFFFFFu;
    const int bidx = blockIdx.x;

    if (bidx < Bn) {
        // ================= FORWARD =================
        const int b = bidx;
        float Eh[64];
#pragma unroll
        for (int i = 0; i < 64; i++)
            Eh[i] = expf(trans[(h * 64 + i) * Kn + j]);

        const float* lg = g_logits + (size_t)b * Tn * Kn;
        wait_chunk(0, tid);

        float alpha = startT[j] + lg[j];
        float e_next = lg[Kn + j];

        for (int t = 1; t < Tn; t++) {
            float emit = e_next;
            if ((t & 63) == 63 && t + 1 < Tn) wait_chunk((t + 1) >> 6, tid);
            if (t + 1 < Tn) e_next = lg[(size_t)(t + 1) * Kn + j];
            int mt = mask[b * Tn + t];

            float wm = alpha;
#pragma unroll
            for (int o = 16; o; o >>= 1)
                wm = fmaxf(wm, __shfl_xor_sync(FULL, wm, o));
            if ((tid & 31) == 0) shred[tid >> 5] = wm;
            __syncthreads();
            float m = shred[0];
#pragma unroll
            for (int w = 1; w < 8; w++) m = fmaxf(m, shred[w]);

            float p = expf(alpha - m);
            if (h == 0) sh_s[j] = p;
            __syncthreads();

            float s = 0.f;
            const float4* p4 = (const float4*)(sh_s + h * 64);
#pragma unroll
            for (int i4 = 0; i4 < 16; i4++) {
                float4 v = p4[i4];
                s += v.x * Eh[i4 * 4 + 0];
                s += v.y * Eh[i4 * 4 + 1];
                s += v.z * Eh[i4 * 4 + 2];
                s += v.w * Eh[i4 * 4 + 3];
            }
            s += __shfl_xor_sync(FULL, s, 1);
            float nxt = m + logf(s) + emit;
            alpha = (mt > 0) ? nxt : alpha;
        }

        // logZ
        __syncthreads();
        float v = alpha + endT[j];
        float wm = v;
#pragma unroll
        for (int o = 16; o; o >>= 1)
            wm = fmaxf(wm, __shfl_xor_sync(FULL, wm, o));
        if ((tid & 31) == 0) shred[tid >> 5] = wm;
        __syncthreads();
        float m = shred[0];
#pragma unroll
        for (int w = 1; w < 8; w++) m = fmaxf(m, shred[w]);
        __syncthreads();
        float pc = (h == 0) ? expf(v - m) : 0.f;
#pragma unroll
        for (int o = 16; o; o >>= 1)
            pc += __shfl_xor_sync(FULL, pc, o);
        if ((tid & 31) == 0) shred[tid >> 5] = pc;
        __syncthreads();
        float Z = 0.f;
#pragma unroll
        for (int w = 0; w < 8; w++) Z += shred[w];
        float logZ = m + logf(Z);
        __syncthreads();

        // path score
        float sc = 0.f;
        int msum = 0;
        for (int t = tid; t < Tn; t += 256) {
            msum += mask[b * Tn + t];
            if (t >= 1) {
                int cur  = labels[b * Tn + t];
                int prev = labels[b * Tn + t - 1];
                float mf = (float)mask[b * Tn + t];
                sc += (trans[prev * Kn + cur] + lg[(size_t)t * Kn + cur]) * mf;
            }
        }
#pragma unroll
        for (int o = 16; o; o >>= 1) {
            sc   += __shfl_xor_sync(FULL, sc, o);
            msum += __shfl_xor_sync(FULL, msum, o);
        }
        if ((tid & 31) == 0) { shred[tid >> 5] = sc; shredi[tid >> 5] = msum; }
        __syncthreads();
        if (tid == 0) {
            float S = 0.f; int Mc = 0;
#pragma unroll
            for (int w = 0; w < 8; w++) { S += shred[w]; Mc += shredi[w]; }
            int l0 = labels[b * Tn];
            S += startT[l0] + lg[l0];
            int last = labels[b * Tn + (Mc - 1)];
            S += endT[last];
            g_llh[b] = S - logZ;
        }
    } else {
        // ================= VITERBI =================
        const int b = bidx - Bn;
        float Th[64];
#pragma unroll
        for (int i = 0; i < 64; i++)
            Th[i] = trans[(h * 64 + i) * Kn + j];

        const float* lg = g_logits + (size_t)b * Tn * Kn;
        wait_chunk(0, tid);

        float sj = startT[j] + lg[j];
        if (h == 0) sh_s[j] = sj;
        float e_next = lg[Kn + j];
        __syncthreads();

        for (int t = 1; t < Tn; t++) {
            float emit = e_next;
            if ((t & 63) == 63 && t + 1 < Tn) wait_chunk((t + 1) >> 6, tid);
            if (t + 1 < Tn) e_next = lg[(size_t)(t + 1) * Kn + j];
            int mt = mask[b * Tn + t];

            float best = -3.4e38f;
            int arg = 0;
            const float4* s4 = (const float4*)(sh_s + h * 64);
#pragma unroll
            for (int i4 = 0; i4 < 16; i4++) {
                float4 v = s4[i4];
                float c0 = v.x + Th[i4 * 4 + 0];
                float c1 = v.y + Th[i4 * 4 + 1];
                float c2 = v.z + Th[i4 * 4 + 2];
                float c3 = v.w + Th[i4 * 4 + 3];
                if (c0 > best) { best = c0; arg = i4 * 4 + 0; }
                if (c1 > best) { best = c1; arg = i4 * 4 + 1; }
                if (c2 > best) { best = c2; arg = i4 * 4 + 2; }
                if (c3 > best) { best = c3; arg = i4 * 4 + 3; }
            }
            int ai = h * 64 + arg;
            float ob = __shfl_xor_sync(FULL, best, 1);
            int   oi = __shfl_xor_sync(FULL, ai, 1);
            float lb = (h == 0) ? best : ob;
            int   li = (h == 0) ? ai   : oi;
            float hb = (h == 0) ? ob   : best;
            int   hi = (h == 0) ? oi   : ai;
            float fb; int fa;
            if (hb > lb) { fb = hb; fa = hi; } else { fb = lb; fa = li; }

            float ns; int bpv;
            if (mt > 0) { ns = fb + emit; bpv = fa; }
            else        { ns = sj;        bpv = j;  }
            sj = ns;
            __syncthreads();
            if (h == 0) {
                sh_s[j] = sj;
                bp[(size_t)(t - 1) * Kn + j] = (unsigned char)bpv;
            }
            __syncthreads();
        }

        if (h == 0) sh_s[j] = sj + endT[j];
        __syncthreads();
        if (tid == 0) {
            float bbest = sh_s[0];
            int btag = 0;
            for (int q = 1; q < Kn; q++) {
                float vv = sh_s[q];
                if (vv > bbest) { bbest = vv; btag = q; }
            }
            int tag = btag;
            out[b * Tn + (Tn - 1)] = (float)tag;
            for (int t = Tn - 2; t >= 0; t--) {
                tag = bp[(size_t)t * Kn + tag];
                out[b * Tn + t] = (float)tag;
            }
        }
    }
}

// ---------------------------------------------------------------------------
// loss = -mean(llh)
// ---------------------------------------------------------------------------
__global__ void loss_kernel(float* __restrict__ out)
{
    const unsigned FULL = 0xFFFFFFFFu;
    float v = (threadIdx.x < Bn) ? g_llh[threadIdx.x] : 0.f;
#pragma unroll
    for (int o = 16; o; o >>= 1) v += __shfl_xor_sync(FULL, v, o);
    if (threadIdx.x == 0) out[Bn * Tn] = -(v / (float)Bn);
}

extern "C" void kernel_launch(void* const* d_in, const int* in_sizes, int n_in,
                              void* d_out, int out_size)
{
    const float* hiddens = (const float*)d_in[0];
    const int*   mask    = (const int*)d_in[1];
    const int*   labels  = (const int*)d_in[2];
    const float* W       = (const float*)d_in[3];
    const float* bias    = (const float*)d_in[4];
    const float* startT  = (const float*)d_in[5];
    const float* endT    = (const float*)d_in[6];
    const float* trans   = (const float*)d_in[7];
    float* out = (float*)d_out;

    // lazily created side stream + events (first call is the uncaptured
    // correctness run; reused as-is inside graph capture via fork/join)
    static cudaStream_t s_side = nullptr;
    static cudaEvent_t  e_fork = nullptr, e_join = nullptr;
    if (!s_side) {
        cudaStreamCreateWithFlags(&s_side, cudaStreamNonBlocking);
        cudaEventCreateWithFlags(&e_fork, cudaEventDisableTiming);
        cudaEventCreateWithFlags(&e_join, cudaEventDisableTiming);
        cudaFuncSetAttribute(crf_kernel,
                             cudaFuncAttributeMaxDynamicSharedMemorySize,
                             SMEM_BYTES);
    }

    init_kernel<<<1, 32>>>();
    cudaEventRecord(e_fork, 0);

    // branch A (main stream): producer
    gemm_kernel<<<8 * Bn, 256>>>(hiddens, W, bias);

    // branch B (side stream): consumer, gated by chunk counters
    cudaStreamWaitEvent(s_side, e_fork, 0);
    crf_kernel<<<2 * Bn, 256, SMEM_BYTES, s_side>>>(
        mask, labels, startT, endT, trans, out);
    cudaEventRecord(e_join, s_side);

    // join + epilogue
    cudaStreamWaitEvent(0, e_join, 0);
    loss_kernel<<<1, 32>>>(out);
}

// round 15
// speedup vs baseline: 2.1245x; 2.1245x over previous
#include <cuda_runtime.h>
#include <math.h>

#define Bn 32
#define Tn 512
#define Hn 2048
#define Kn 128

#define NWORK  160          // persistent GEMM worker blocks
#define NTILES 256          // 8 chunks * 32 tiles (tile = 64 timesteps of 1 batch)
#define TPC    32           // tiles per chunk

// Scratch (no allocations allowed)
__device__ float g_logits[Bn * Tn * Kn];   // 8 MB
__device__ float g_llh[Bn];
__device__ int   g_cnt[8];                 // tiles completed per chunk
__device__ int   g_ticket;                 // GEMM work ticket
__device__ int   g_fwd_done;               // forward blocks completed

// CRF view : [0,512) sh_s | [512,768) shred | [768,1024) shredi | [1024,..) bp
// GEMM view: [0,4096) As[16][64] | [4096,12288) Bs[16][128] | [12544) sh_tk
#define SMEM_BYTES (1024 + (Tn - 1) * Kn)

__global__ void init_kernel()
{
    if (threadIdx.x < 8) g_cnt[threadIdx.x] = 0;
    if (threadIdx.x == 0) { g_ticket = 0; g_fwd_done = 0; }
}

__device__ __forceinline__ void wait_chunk(int c, int tid)
{
    if (tid == 0) {
        while (((volatile int*)g_cnt)[c] < TPC) __nanosleep(128);
    }
    __syncthreads();
    __threadfence();
}

// ---------------------------------------------------------------------------
// Fused kernel. 224 blocks x 256 threads.
//   bids [0,32)   : forward logsumexp + path score -> g_llh[b]; last one: loss
//   bids [32,64)  : viterbi decode -> out tags
//   bids [64,224) : persistent GEMM workers (R1 BM=64 config, chunk-major)
// ---------------------------------------------------------------------------
__global__ __launch_bounds__(256) void fused_kernel(
    const float* __restrict__ hid, const float* __restrict__ W,
    const float* __restrict__ bias,
    const int* __restrict__ mask, const int* __restrict__ labels,
    const float* __restrict__ startT, const float* __restrict__ endT,
    const float* __restrict__ trans, float* __restrict__ out)
{
    extern __shared__ char smem[];
    const int tid  = threadIdx.x;
    const int bidx = blockIdx.x;
    const unsigned FULL = 0xFFFFFFFFu;

    if (bidx >= 2 * Bn) {
        // ================= GEMM workers (R1 BM=64 body) =================
        float (*As)[64]  = (float(*)[64])smem;            // [16][64]
        float (*Bs)[128] = (float(*)[128])(smem + 4096);  // [16][128]
        int* sh_tk = (int*)(smem + 12544);

        const int ty  = tid >> 5;
        const int tx  = tid & 31;
        const int arow = tid >> 2;
        const int ac4  = (tid & 3) * 4;

        for (;;) {
            if (tid == 0) *sh_tk = atomicAdd(&g_ticket, 1);
            __syncthreads();
            const int tk = *sh_tk;
            __syncthreads();
            if (tk >= NTILES) break;

            const int c  = tk >> 5;          // chunk 0..7
            const int b  = tk & 31;          // batch
            const int m0 = b * Tn + c * 64;

            float acc[8][4];
#pragma unroll
            for (int i = 0; i < 8; i++)
#pragma unroll
                for (int jj = 0; jj < 4; jj++) acc[i][jj] = 0.f;

            for (int k0 = 0; k0 < Hn; k0 += 16) {
                float4 a4 = *(const float4*)(hid + (size_t)(m0 + arow) * Hn + k0 + ac4);
                As[ac4 + 0][arow] = a4.x;
                As[ac4 + 1][arow] = a4.y;
                As[ac4 + 2][arow] = a4.z;
                As[ac4 + 3][arow] = a4.w;
                {
                    int idx = tid;
                    int r = idx >> 5, cc = (idx & 31) * 4;
                    *(float4*)(&Bs[r][cc]) =
                        *(const float4*)(W + (size_t)(k0 + r) * Kn + cc);
                    idx = tid + 256;
                    r = idx >> 5; cc = (idx & 31) * 4;
                    *(float4*)(&Bs[r][cc]) =
                        *(const float4*)(W + (size_t)(k0 + r) * Kn + cc);
                }
                __syncthreads();

#pragma unroll
                for (int k = 0; k < 16; k++) {
                    float4 b4 = *(const float4*)(&Bs[k][tx * 4]);
                    float a[8];
#pragma unroll
                    for (int i = 0; i < 8; i++) a[i] = As[k][ty * 8 + i];
#pragma unroll
                    for (int i = 0; i < 8; i++) {
                        acc[i][0] += a[i] * b4.x;
                        acc[i][1] += a[i] * b4.y;
                        acc[i][2] += a[i] * b4.z;
                        acc[i][3] += a[i] * b4.w;
                    }
                }
                __syncthreads();
            }

            const int n0 = tx * 4;
            float4 bb = *(const float4*)(bias + n0);
#pragma unroll
            for (int i = 0; i < 8; i++) {
                int row = m0 + ty * 8 + i;
                float4 o;
                o.x = acc[i][0] + bb.x;
                o.y = acc[i][1] + bb.y;
                o.z = acc[i][2] + bb.z;
                o.w = acc[i][3] + bb.w;
                *(float4*)(g_logits + (size_t)row * Kn + n0) = o;
            }
            __threadfence();
            __syncthreads();
            if (tid == 0) atomicAdd(&g_cnt[c], 1);
        }
        return;
    }

    // ================= CRF =================
    float* sh_s   = (float*)smem;                 // 128 floats
    float* shred  = (float*)(smem + 512);
    int*   shredi = (int*)(smem + 512 + 256);
    unsigned char* bp = (unsigned char*)(smem + 1024);

    const int j = tid >> 1, h = tid & 1;

    if (bidx < Bn) {
        // ---------------- FORWARD ----------------
        const int b = bidx;
        float Eh[64];
#pragma unroll
        for (int i = 0; i < 64; i++)
            Eh[i] = expf(trans[(h * 64 + i) * Kn + j]);

        const float* lg = g_logits + (size_t)b * Tn * Kn;
        wait_chunk(0, tid);

        float alpha = startT[j] + lg[j];
        float e_next = lg[Kn + j];

        for (int t = 1; t < Tn; t++) {
            float emit = e_next;
            if ((t & 63) == 63 && t + 1 < Tn) wait_chunk((t + 1) >> 6, tid);
            if (t + 1 < Tn) e_next = lg[(size_t)(t + 1) * Kn + j];
            int mt = mask[b * Tn + t];

            float wm = alpha;
#pragma unroll
            for (int o = 16; o; o >>= 1)
                wm = fmaxf(wm, __shfl_xor_sync(FULL, wm, o));
            if ((tid & 31) == 0) shred[tid >> 5] = wm;
            __syncthreads();
            float m = shred[0];
#pragma unroll
            for (int w = 1; w < 8; w++) m = fmaxf(m, shred[w]);

            float p = expf(alpha - m);
            if (h == 0) sh_s[j] = p;
            __syncthreads();

            float s = 0.f;
            const float4* p4 = (const float4*)(sh_s + h * 64);
#pragma unroll
            for (int i4 = 0; i4 < 16; i4++) {
                float4 v = p4[i4];
                s += v.x * Eh[i4 * 4 + 0];
                s += v.y * Eh[i4 * 4 + 1];
                s += v.z * Eh[i4 * 4 + 2];
                s += v.w * Eh[i4 * 4 + 3];
            }
            s += __shfl_xor_sync(FULL, s, 1);
            float nxt = m + logf(s) + emit;
            alpha = (mt > 0) ? nxt : alpha;
        }

        // logZ
        __syncthreads();
        float v = alpha + endT[j];
        float wm = v;
#pragma unroll
        for (int o = 16; o; o >>= 1)
            wm = fmaxf(wm, __shfl_xor_sync(FULL, wm, o));
        if ((tid & 31) == 0) shred[tid >> 5] = wm;
        __syncthreads();
        float m = shred[0];
#pragma unroll
        for (int w = 1; w < 8; w++) m = fmaxf(m, shred[w]);
        __syncthreads();
        float pc = (h == 0) ? expf(v - m) : 0.f;
#pragma unroll
        for (int o = 16; o; o >>= 1)
            pc += __shfl_xor_sync(FULL, pc, o);
        if ((tid & 31) == 0) shred[tid >> 5] = pc;
        __syncthreads();
        float Z = 0.f;
#pragma unroll
        for (int w = 0; w < 8; w++) Z += shred[w];
        float logZ = m + logf(Z);
        __syncthreads();

        // path score
        float sc = 0.f;
        int msum = 0;
        for (int t = tid; t < Tn; t += 256) {
            msum += mask[b * Tn + t];
            if (t >= 1) {
                int cur  = labels[b * Tn + t];
                int prev = labels[b * Tn + t - 1];
                float mf = (float)mask[b * Tn + t];
                sc += (trans[prev * Kn + cur] + lg[(size_t)t * Kn + cur]) * mf;
            }
        }
#pragma unroll
        for (int o = 16; o; o >>= 1) {
            sc   += __shfl_xor_sync(FULL, sc, o);
            msum += __shfl_xor_sync(FULL, msum, o);
        }
        if ((tid & 31) == 0) { shred[tid >> 5] = sc; shredi[tid >> 5] = msum; }
        __syncthreads();
        if (tid == 0) {
            float S = 0.f; int Mc = 0;
#pragma unroll
            for (int w = 0; w < 8; w++) { S += shred[w]; Mc += shredi[w]; }
            int l0 = labels[b * Tn];
            S += startT[l0] + lg[l0];
            int last = labels[b * Tn + (Mc - 1)];
            S += endT[last];
            g_llh[b] = S - logZ;
            __threadfence();
            int d = atomicAdd(&g_fwd_done, 1);
            if (d == Bn - 1) {              // last fwd block computes the loss
                float T = 0.f;
                for (int i = 0; i < Bn; i++) T += g_llh[i];
                out[Bn * Tn] = -(T / (float)Bn);
            }
        }
    } else {
        // ---------------- VITERBI ----------------
        const int b = bidx - Bn;
        float Th[64];
#pragma unroll
        for (int i = 0; i < 64; i++)
            Th[i] = trans[(h * 64 + i) * Kn + j];

        const float* lg = g_logits + (size_t)b * Tn * Kn;
        wait_chunk(0, tid);

        float sj = startT[j] + lg[j];
        if (h == 0) sh_s[j] = sj;
        float e_next = lg[Kn + j];
        __syncthreads();

        for (int t = 1; t < Tn; t++) {
            float emit = e_next;
            if ((t & 63) == 63 && t + 1 < Tn) wait_chunk((t + 1) >> 6, tid);
            if (t + 1 < Tn) e_next = lg[(size_t)(t + 1) * Kn + j];
            int mt = mask[b * Tn + t];

            float best = -3.4e38f;
            int arg = 0;
            const float4* s4 = (const float4*)(sh_s + h * 64);
#pragma unroll
            for (int i4 = 0; i4 < 16; i4++) {
                float4 v = s4[i4];
                float c0 = v.x + Th[i4 * 4 + 0];
                float c1 = v.y + Th[i4 * 4 + 1];
                float c2 = v.z + Th[i4 * 4 + 2];
                float c3 = v.w + Th[i4 * 4 + 3];
                if (c0 > best) { best = c0; arg = i4 * 4 + 0; }
                if (c1 > best) { best = c1; arg = i4 * 4 + 1; }
                if (c2 > best) { best = c2; arg = i4 * 4 + 2; }
                if (c3 > best) { best = c3; arg = i4 * 4 + 3; }
            }
            int ai = h * 64 + arg;
            float ob = __shfl_xor_sync(FULL, best, 1);
            int   oi = __shfl_xor_sync(FULL, ai, 1);
            float lb = (h == 0) ? best : ob;
            int   li = (h == 0) ? ai   : oi;
            float hb = (h == 0) ? ob   : best;
            int   hi = (h == 0) ? oi   : ai;
            float fb; int fa;
            if (hb > lb) { fb = hb; fa = hi; } else { fb = lb; fa = li; }

            float ns; int bpv;
            if (mt > 0) { ns = fb + emit; bpv = fa; }
            else        { ns = sj;        bpv = j;  }
            sj = ns;
            __syncthreads();
            if (h == 0) {
                sh_s[j] = sj;
                bp[(size_t)(t - 1) * Kn + j] = (unsigned char)bpv;
            }
            __syncthreads();
        }

        if (h == 0) sh_s[j] = sj + endT[j];
        __syncthreads();
        if (tid == 0) {
            float bbest = sh_s[0];
            int btag = 0;
            for (int q = 1; q < Kn; q++) {
                float vv = sh_s[q];
                if (vv > bbest) { bbest = vv; btag = q; }
            }
            int tag = btag;
            out[b * Tn + (Tn - 1)] = (float)tag;
            for (int t = Tn - 2; t >= 0; t--) {
                tag = bp[(size_t)t * Kn + tag];
                out[b * Tn + t] = (float)tag;
            }
        }
    }
}

extern "C" void kernel_launch(void* const* d_in, const int* in_sizes, int n_in,
                              void* d_out, int out_size)
{
    const float* hiddens = (const float*)d_in[0];
    const int*   mask    = (const int*)d_in[1];
    const int*   labels  = (const int*)d_in[2];
    const float* W       = (const float*)d_in[3];
    const float* bias    = (const float*)d_in[4];
    const float* startT  = (const float*)d_in[5];
    const float* endT    = (const float*)d_in[6];
    const float* trans   = (const float*)d_in[7];
    float* out = (float*)d_out;

    init_kernel<<<1, 32>>>();

    cudaFuncSetAttribute(fused_kernel, cudaFuncAttributeMaxDynamicSharedMemorySize,
                         SMEM_BYTES);
    fused_kernel<<<2 * Bn + NWORK, 256, SMEM_BYTES>>>(
        hiddens, W, bias, mask, labels, startT, endT, trans, out);
}

// round 17
// speedup vs baseline: 2.1465x; 1.0103x over previous
#include <cuda_runtime.h>
#include <math.h>

#define Bn 32
#define Tn 512
#define Hn 2048
#define Kn 128

#define NWORK  232          // persistent GEMM worker blocks (64+232=296 = 2/SM)
#define NTILES 256          // 8 chunks * 32 tiles (tile = 64 timesteps of 1 batch)
#define TPC    32           // tiles per chunk

// Scratch (no allocations allowed)
__device__ float g_logits[Bn * Tn * Kn];   // 8 MB
__device__ float g_llh[Bn];
__device__ int   g_cnt[8];                 // tiles completed per chunk
__device__ int   g_ticket;                 // GEMM work ticket
__device__ int   g_fwd_done;               // forward blocks completed

// CRF view : [0,512) sh_s | [512,768) shred | [768,1024) shredi | [1024,..) bp
// GEMM view: [0,4096) As[16][64] | [4096,12288) Bs[16][128] | [12544) sh_tk
#define SMEM_BYTES (1024 + (Tn - 1) * Kn)

__global__ void init_kernel()
{
    if (threadIdx.x < 8) g_cnt[threadIdx.x] = 0;
    if (threadIdx.x == 0) { g_ticket = 0; g_fwd_done = 0; }
}

__device__ __forceinline__ void wait_chunk(int c, int tid)
{
    if (tid == 0) {
        while (((volatile int*)g_cnt)[c] < TPC) __nanosleep(128);
    }
    __syncthreads();
    __threadfence();
}

// ---------------------------------------------------------------------------
// Fused kernel. 296 blocks x 256 threads, 2 blocks/SM.
//   bids [0,32)   : forward logsumexp + path score -> g_llh[b]; last one: loss
//   bids [32,64)  : viterbi decode -> out tags
//   bids [64,296) : persistent GEMM workers (R1 BM=64 config, chunk-major)
// ---------------------------------------------------------------------------
__global__ __launch_bounds__(256, 2) void fused_kernel(
    const float* __restrict__ hid, const float* __restrict__ W,
    const float* __restrict__ bias,
    const int* __restrict__ mask, const int* __restrict__ labels,
    const float* __restrict__ startT, const float* __restrict__ endT,
    const float* __restrict__ trans, float* __restrict__ out)
{
    extern __shared__ char smem[];
    const int tid  = threadIdx.x;
    const int bidx = blockIdx.x;
    const unsigned FULL = 0xFFFFFFFFu;

    if (bidx >= 2 * Bn) {
        // ================= GEMM workers (R1 BM=64 body) =================
        float (*As)[64]  = (float(*)[64])smem;            // [16][64]
        float (*Bs)[128] = (float(*)[128])(smem + 4096);  // [16][128]
        int* sh_tk = (int*)(smem + 12544);

        const int ty  = tid >> 5;
        const int tx  = tid & 31;
        const int arow = tid >> 2;
        const int ac4  = (tid & 3) * 4;

        for (;;) {
            if (tid == 0) *sh_tk = atomicAdd(&g_ticket, 1);
            __syncthreads();
            const int tk = *sh_tk;
            __syncthreads();
            if (tk >= NTILES) break;

            const int c  = tk >> 5;          // chunk 0..7
            const int b  = tk & 31;          // batch
            const int m0 = b * Tn + c * 64;

            float acc[8][4];
#pragma unroll
            for (int i = 0; i < 8; i++)
#pragma unroll
                for (int jj = 0; jj < 4; jj++) acc[i][jj] = 0.f;

            for (int k0 = 0; k0 < Hn; k0 += 16) {
                float4 a4 = *(const float4*)(hid + (size_t)(m0 + arow) * Hn + k0 + ac4);
                As[ac4 + 0][arow] = a4.x;
                As[ac4 + 1][arow] = a4.y;
                As[ac4 + 2][arow] = a4.z;
                As[ac4 + 3][arow] = a4.w;
                {
                    int idx = tid;
                    int r = idx >> 5, cc = (idx & 31) * 4;
                    *(float4*)(&Bs[r][cc]) =
                        *(const float4*)(W + (size_t)(k0 + r) * Kn + cc);
                    idx = tid + 256;
                    r = idx >> 5; cc = (idx & 31) * 4;
                    *(float4*)(&Bs[r][cc]) =
                        *(const float4*)(W + (size_t)(k0 + r) * Kn + cc);
                }
                __syncthreads();

#pragma unroll
                for (int k = 0; k < 16; k++) {
                    float4 b4 = *(const float4*)(&Bs[k][tx * 4]);
                    float a[8];
#pragma unroll
                    for (int i = 0; i < 8; i++) a[i] = As[k][ty * 8 + i];
#pragma unroll
                    for (int i = 0; i < 8; i++) {
                        acc[i][0] += a[i] * b4.x;
                        acc[i][1] += a[i] * b4.y;
                        acc[i][2] += a[i] * b4.z;
                        acc[i][3] += a[i] * b4.w;
                    }
                }
                __syncthreads();
            }

            const int n0 = tx * 4;
            float4 bb = *(const float4*)(bias + n0);
#pragma unroll
            for (int i = 0; i < 8; i++) {
                int row = m0 + ty * 8 + i;
                float4 o;
                o.x = acc[i][0] + bb.x;
                o.y = acc[i][1] + bb.y;
                o.z = acc[i][2] + bb.z;
                o.w = acc[i][3] + bb.w;
                *(float4*)(g_logits + (size_t)row * Kn + n0) = o;
            }
            __threadfence();
            __syncthreads();
            if (tid == 0) atomicAdd(&g_cnt[c], 1);
        }
        return;
    }

    // ================= CRF =================
    float* sh_s   = (float*)smem;                 // 128 floats
    float* shred  = (float*)(smem + 512);
    int*   shredi = (int*)(smem + 512 + 256);
    unsigned char* bp = (unsigned char*)(smem + 1024);

    const int j = tid >> 1, h = tid & 1;

    if (bidx < Bn) {
        // ---------------- FORWARD ----------------
        const int b = bidx;
        float Eh[64];
#pragma unroll
        for (int i = 0; i < 64; i++)
            Eh[i] = expf(trans[(h * 64 + i) * Kn + j]);

        const float* lg = g_logits + (size_t)b * Tn * Kn;
        wait_chunk(0, tid);

        float alpha = startT[j] + lg[j];
        float e_next = lg[Kn + j];

        for (int t = 1; t < Tn; t++) {
            float emit = e_next;
            if ((t & 63) == 63 && t + 1 < Tn) wait_chunk((t + 1) >> 6, tid);
            if (t + 1 < Tn) e_next = lg[(size_t)(t + 1) * Kn + j];
            int mt = mask[b * Tn + t];

            float wm = alpha;
#pragma unroll
            for (int o = 16; o; o >>= 1)
                wm = fmaxf(wm, __shfl_xor_sync(FULL, wm, o));
            if ((tid & 31) == 0) shred[tid >> 5] = wm;
            __syncthreads();
            float m = shred[0];
#pragma unroll
            for (int w = 1; w < 8; w++) m = fmaxf(m, shred[w]);

            float p = expf(alpha - m);
            if (h == 0) sh_s[j] = p;
            __syncthreads();

            float s = 0.f;
            const float4* p4 = (const float4*)(sh_s + h * 64);
#pragma unroll
            for (int i4 = 0; i4 < 16; i4++) {
                float4 v = p4[i4];
                s += v.x * Eh[i4 * 4 + 0];
                s += v.y * Eh[i4 * 4 + 1];
                s += v.z * Eh[i4 * 4 + 2];
                s += v.w * Eh[i4 * 4 + 3];
            }
            s += __shfl_xor_sync(FULL, s, 1);
            float nxt = m + logf(s) + emit;
            alpha = (mt > 0) ? nxt : alpha;
        }

        // logZ
        __syncthreads();
        float v = alpha + endT[j];
        float wm = v;
#pragma unroll
        for (int o = 16; o; o >>= 1)
            wm = fmaxf(wm, __shfl_xor_sync(FULL, wm, o));
        if ((tid & 31) == 0) shred[tid >> 5] = wm;
        __syncthreads();
        float m = shred[0];
#pragma unroll
        for (int w = 1; w < 8; w++) m = fmaxf(m, shred[w]);
        __syncthreads();
        float pc = (h == 0) ? expf(v - m) : 0.f;
#pragma unroll
        for (int o = 16; o; o >>= 1)
            pc += __shfl_xor_sync(FULL, pc, o);
        if ((tid & 31) == 0) shred[tid >> 5] = pc;
        __syncthreads();
        float Z = 0.f;
#pragma unroll
        for (int w = 0; w < 8; w++) Z += shred[w];
        float logZ = m + logf(Z);
        __syncthreads();

        // path score
        float sc = 0.f;
        int msum = 0;
        for (int t = tid; t < Tn; t += 256) {
            msum += mask[b * Tn + t];
            if (t >= 1) {
                int cur  = labels[b * Tn + t];
                int prev = labels[b * Tn + t - 1];
                float mf = (float)mask[b * Tn + t];
                sc += (trans[prev * Kn + cur] + lg[(size_t)t * Kn + cur]) * mf;
            }
        }
#pragma unroll
        for (int o = 16; o; o >>= 1) {
            sc   += __shfl_xor_sync(FULL, sc, o);
            msum += __shfl_xor_sync(FULL, msum, o);
        }
        if ((tid & 31) == 0) { shred[tid >> 5] = sc; shredi[tid >> 5] = msum; }
        __syncthreads();
        if (tid == 0) {
            float S = 0.f; int Mc = 0;
#pragma unroll
            for (int w = 0; w < 8; w++) { S += shred[w]; Mc += shredi[w]; }
            int l0 = labels[b * Tn];
            S += startT[l0] + lg[l0];
            int last = labels[b * Tn + (Mc - 1)];
            S += endT[last];
            g_llh[b] = S - logZ;
            __threadfence();
            int d = atomicAdd(&g_fwd_done, 1);
            if (d == Bn - 1) {              // last fwd block computes the loss
                float T = 0.f;
                for (int i = 0; i < Bn; i++) T += g_llh[i];
                out[Bn * Tn] = -(T / (float)Bn);
            }
        }
    } else {
        // ---------------- VITERBI ----------------
        const int b = bidx - Bn;
        float Th[64];
#pragma unroll
        for (int i = 0; i < 64; i++)
            Th[i] = trans[(h * 64 + i) * Kn + j];

        const float* lg = g_logits + (size_t)b * Tn * Kn;
        wait_chunk(0, tid);

        float sj = startT[j] + lg[j];
        if (h == 0) sh_s[j] = sj;
        float e_next = lg[Kn + j];
        __syncthreads();

        for (int t = 1; t < Tn; t++) {
            float emit = e_next;
            if ((t & 63) == 63 && t + 1 < Tn) wait_chunk((t + 1) >> 6, tid);
            if (t + 1 < Tn) e_next = lg[(size_t)(t + 1) * Kn + j];
            int mt = mask[b * Tn + t];

            float best = -3.4e38f;
            int arg = 0;
            const float4* s4 = (const float4*)(sh_s + h * 64);
#pragma unroll
            for (int i4 = 0; i4 < 16; i4++) {
                float4 v = s4[i4];
                float c0 = v.x + Th[i4 * 4 + 0];
                float c1 = v.y + Th[i4 * 4 + 1];
                float c2 = v.z + Th[i4 * 4 + 2];
                float c3 = v.w + Th[i4 * 4 + 3];
                if (c0 > best) { best = c0; arg = i4 * 4 + 0; }
                if (c1 > best) { best = c1; arg = i4 * 4 + 1; }
                if (c2 > best) { best = c2; arg = i4 * 4 + 2; }
                if (c3 > best) { best = c3; arg = i4 * 4 + 3; }
            }
            int ai = h * 64 + arg;
            float ob = __shfl_xor_sync(FULL, best, 1);
            int   oi = __shfl_xor_sync(FULL, ai, 1);
            float lb = (h == 0) ? best : ob;
            int   li = (h == 0) ? ai   : oi;
            float hb = (h == 0) ? ob   : best;
            int   hi = (h == 0) ? oi   : ai;
            float fb; int fa;
            if (hb > lb) { fb = hb; fa = hi; } else { fb = lb; fa = li; }

            float ns; int bpv;
            if (mt > 0) { ns = fb + emit; bpv = fa; }
            else        { ns = sj;        bpv = j;  }
            sj = ns;
            __syncthreads();
            if (h == 0) {
                sh_s[j] = sj;
                bp[(size_t)(t - 1) * Kn + j] = (unsigned char)bpv;
            }
            __syncthreads();
        }

        if (h == 0) sh_s[j] = sj + endT[j];
        __syncthreads();
        if (tid == 0) {
            float bbest = sh_s[0];
            int btag = 0;
            for (int q = 1; q < Kn; q++) {
                float vv = sh_s[q];
                if (vv > bbest) { bbest = vv; btag = q; }
            }
            int tag = btag;
            out[b * Tn + (Tn - 1)] = (float)tag;
            for (int t = Tn - 2; t >= 0; t--) {
                tag = bp[(size_t)t * Kn + tag];
                out[b * Tn + t] = (float)tag;
            }
        }
    }
}

extern "C" void kernel_launch(void* const* d_in, const int* in_sizes, int n_in,
                              void* d_out, int out_size)
{
    const float* hiddens = (const float*)d_in[0];
    const int*   mask    = (const int*)d_in[1];
    const int*   labels  = (const int*)d_in[2];
    const float* W       = (const float*)d_in[3];
    const float* bias    = (const float*)d_in[4];
    const float* startT  = (const float*)d_in[5];
    const float* endT    = (const float*)d_in[6];
    const float* trans   = (const float*)d_in[7];
    float* out = (float*)d_out;

    init_kernel<<<1, 32>>>();

    cudaFuncSetAttribute(fused_kernel, cudaFuncAttributeMaxDynamicSharedMemorySize,
                         SMEM_BYTES);
    fused_kernel<<<2 * Bn + NWORK, 256, SMEM_BYTES>>>(
        hiddens, W, bias, mask, labels, startT, endT, trans, out);
}